// round 13
// baseline (speedup 1.0000x reference)
#include <cuda_runtime.h>
#include <cuda_fp16.h>

#define NI 2000      // inner tree nodes
#define NL 10000     // leaves / vocab
#define ND 128       // docs
#define PP 2048      // padded proj width
#define FC 64        // mass feature chunk
#define NMASS_CH 157 // ceil(NL/FC)
#define AG_BLKS 400  // argmax: 10 float4-col blocks x 40 row-chunks
#define AG_CH 50     // rows per argmax chunk
#define AG_RB 10     // load batch (MLP)
#define MP_BLKS (3 * NMASS_CH)   // 471
#define SROWH 68     // half2 row stride per feature-pair
// proj-pair: 32-doc tiles, 64-f chunks, 2x2 micro (R11-verified config)
#define PT 32
#define PSROW 36
#define NPP 10
#define PP_BLKS (NPP * (PP / FC))   // 320
// block-class offsets in the mega kernel
#define O_MP  AG_BLKS                       // 400
#define O_PR  (O_MP + MP_BLKS)              // 871
#define O_PPB (O_PR + ND)                   // 999
#define TOTAL (O_PPB + PP_BLKS + (ND * ND) / 256)   // 1383

__device__ unsigned long long g_amax[NL];
__device__ float g_proj[ND * PP];
__device__ float g_S[ND];
__device__ unsigned g_cnt_amax;
__device__ unsigned g_cnt_proj;

__constant__ int c_it[NPP] = {0,0,0,0,1,1,1,2,2,3};
__constant__ int c_jt[NPP] = {0,1,2,3,1,2,3,2,3,3};

__device__ __forceinline__ __half2 u2h2(unsigned u) {
    return *reinterpret_cast<__half2*>(&u);
}
__device__ __forceinline__ unsigned long long pack_key(float v, int idx) {
    unsigned u = __float_as_uint(v);
    u = (u & 0x80000000u) ? ~u : (u | 0x80000000u);
    return ((unsigned long long)u << 32) | (unsigned)idx;
}
__device__ __forceinline__ void spin_until(unsigned* cnt, unsigned target) {
    // one thread polls, whole block releases together; acquire via threadfence
    if (threadIdx.x == 0) {
        while (atomicAdd(cnt, 0u) < target) __nanosleep(128);
    }
    __syncthreads();
    __threadfence();
}

// ---------------------------------------------------------------- init
__global__ void k_init(float* __restrict__ out) {
    int i = blockIdx.x * blockDim.x + threadIdx.x;
    if (i < NL) g_amax[i] = 0ull;
    if (i < ND * ND) out[i] = 0.0f;
    if (i < ND) g_S[i] = 0.0f;
    if (i == 0) { g_cnt_amax = 0u; g_cnt_proj = 0u; }
}

// ---------------------------------------------------------------- mega kernel: argmax | masspair | proj | projpair
__global__ void __launch_bounds__(256)
k_mega(const float* __restrict__ mass, const float* __restrict__ param,
       float* __restrict__ out) {
    __shared__ union {
        __half2 mp[2][32 * SROWH];
        struct { float s[NI]; float red[256]; } pj;
        struct { float sa[FC * PSROW]; float sb[FC * PSROW]; } pp;
    } sm;
    int tid = threadIdx.x;
    int bid = blockIdx.x;

    if (bid < O_MP) {
        // ================= class A: column argmax of param =================
        int j4 = (bid % 10) * 256 + tid;            // float4 column
        if (j4 < NL / 4) {
            int r0 = (bid / 10) * AG_CH;
            const float4* p = (const float4*)param + (size_t)r0 * (NL / 4) + j4;
            float4 bv = make_float4(-3.4e38f, -3.4e38f, -3.4e38f, -3.4e38f);
            int ix = r0, iy = r0, iz = r0, iw = r0;
            for (int rb = 0; rb < AG_CH; rb += AG_RB) {
                float4 v[AG_RB];
                #pragma unroll
                for (int k = 0; k < AG_RB; k++)
                    v[k] = p[(size_t)(rb + k) * (NL / 4)];
                #pragma unroll
                for (int k = 0; k < AG_RB; k++) {
                    int r = r0 + rb + k;
                    if (v[k].x > bv.x) { bv.x = v[k].x; ix = r; }
                    if (v[k].y > bv.y) { bv.y = v[k].y; iy = r; }
                    if (v[k].z > bv.z) { bv.z = v[k].z; iz = r; }
                    if (v[k].w > bv.w) { bv.w = v[k].w; iw = r; }
                }
            }
            int j = 4 * j4;
            atomicMax(&g_amax[j + 0], pack_key(bv.x, ix));
            atomicMax(&g_amax[j + 1], pack_key(bv.y, iy));
            atomicMax(&g_amax[j + 2], pack_key(bv.z, iz));
            atomicMax(&g_amax[j + 3], pack_key(bv.w, iw));
        }
        __threadfence();
        __syncthreads();
        if (tid == 0) atomicAdd(&g_cnt_amax, 1u);

    } else if (bid < O_PR) {
        // ================= class B: fp16 mass-pair =================
        int pid = bid - O_MP;
        int tp = pid % 3;                 // 0:(0,0) 1:(0,1)+mirror 2:(1,1)
        int chunk = pid / 3;
        int fb = chunk * FC;
        int nh = min(FC, NL - fb) >> 1;
        int it = (tp == 2) ? 1 : 0;
        int jt = (tp == 0) ? 0 : 1;
        __half2* sa2 = sm.mp[0];
        __half2* sb2 = sm.mp[1];

        const __half2 hz = __float2half2_rn(0.0f);
        #pragma unroll
        for (int k = 0; k < 8; k++) {
            int idx = tid + k * 256;          // 0..2047
            int f2 = idx & 31;
            int row = idx >> 5;               // 0..63
            __half2 ha = hz, hb = hz;
            if (f2 < nh) {
                float2 va = *(const float2*)&mass[(size_t)(it * 64 + row) * NL + fb + 2 * f2];
                float2 vb = *(const float2*)&mass[(size_t)(jt * 64 + row) * NL + fb + 2 * f2];
                ha = __floats2half2_rn(va.x, va.y);
                hb = __floats2half2_rn(vb.x, vb.y);
            }
            sa2[f2 * SROWH + row] = ha;
            sb2[f2 * SROWH + row] = hb;
        }
        __syncthreads();

        int tx = tid & 15, ty = tid >> 4;
        __half2 acc[4][4];
        #pragma unroll
        for (int r = 0; r < 4; r++)
            #pragma unroll
            for (int c = 0; c < 4; c++) acc[r][c] = hz;

        #pragma unroll 4
        for (int f2 = 0; f2 < 32; f2++) {
            uint4 ua = *(const uint4*)&sa2[f2 * SROWH + ty * 4];
            uint4 ub = *(const uint4*)&sb2[f2 * SROWH + tx * 4];
            __half2 ar[4] = {u2h2(ua.x), u2h2(ua.y), u2h2(ua.z), u2h2(ua.w)};
            __half2 br[4] = {u2h2(ub.x), u2h2(ub.y), u2h2(ub.z), u2h2(ub.w)};
            #pragma unroll
            for (int r = 0; r < 4; r++)
                #pragma unroll
                for (int c = 0; c < 4; c++)
                    acc[r][c] = __hadd2(acc[r][c], __hmin2(ar[r], br[c]));
        }

        int ib = it * 64 + ty * 4, jb = jt * 64 + tx * 4;
        #pragma unroll
        for (int r = 0; r < 4; r++)
            #pragma unroll
            for (int c = 0; c < 4; c++) {
                float2 f = __half22float2(acc[r][c]);
                float v = -2.0f * (f.x + f.y);
                atomicAdd(&out[(ib + r) * ND + (jb + c)], v);
                if (tp == 1)
                    atomicAdd(&out[(jb + c) * ND + (ib + r)], v);
            }

    } else if (bid < O_PPB) {
        // ================= class C: proj scatter + tree-sum (1 doc) =================
        spin_until(&g_cnt_amax, AG_BLKS);
        int d = bid - O_PR;
        float* s = sm.pj.s;
        for (int i = tid; i < NI; i += 256) s[i] = 0.0f;
        __syncthreads();
        const float4* m4 = (const float4*)(mass + (size_t)d * NL);
        float msum = 0.0f;
        for (int j4 = tid; j4 < NL / 4; j4 += 256) {
            float4 v = m4[j4];
            msum += v.x + v.y + v.z + v.w;
            int a0 = (int)(unsigned)(__ldg(&g_amax[4 * j4 + 0]) & 0xFFFFFFFFull);
            int a1 = (int)(unsigned)(__ldg(&g_amax[4 * j4 + 1]) & 0xFFFFFFFFull);
            int a2 = (int)(unsigned)(__ldg(&g_amax[4 * j4 + 2]) & 0xFFFFFFFFull);
            int a3 = (int)(unsigned)(__ldg(&g_amax[4 * j4 + 3]) & 0xFFFFFFFFull);
            atomicAdd(&s[a0], v.x);
            atomicAdd(&s[a1], v.y);
            atomicAdd(&s[a2], v.z);
            atomicAdd(&s[a3], v.w);
        }
        __syncthreads();
        const int lo[5] = {156, 31, 6, 1, 0};
        const int hi[5] = {399, 155, 30, 5, 0};
        for (int L = 0; L < 5; L++) {
            for (int p = lo[L] + tid; p <= hi[L]; p += 256) {
                float acc = s[p];
                int c0 = 5 * p + 1;
                #pragma unroll
                for (int c = 0; c < 5; c++)
                    if (c0 + c < NI) acc += s[c0 + c];
                s[p] = acc;
            }
            __syncthreads();
        }
        float psum = 0.0f;
        for (int i = tid; i < NI; i += 256) psum += s[i];
        sm.pj.red[tid] = msum + psum;
        __syncthreads();
        for (int w = 128; w > 0; w >>= 1) {
            if (tid < w) sm.pj.red[tid] += sm.pj.red[tid + w];
            __syncthreads();
        }
        if (tid == 0) g_S[d] = sm.pj.red[0];
        float* gp = g_proj + (size_t)d * PP;
        for (int i = tid; i < PP; i += 256)
            gp[i] = (i < NI) ? s[i] : 0.0f;
        __threadfence();
        __syncthreads();
        if (tid == 0) atomicAdd(&g_cnt_proj, 1u);

    } else {
        // ================= class D: proj-pair + S epilogue =================
        spin_until(&g_cnt_proj, ND);
        int pid = bid - O_PPB;
        if (pid < PP_BLKS) {
            int tp = pid % NPP;
            int fb = (pid / NPP) * FC;
            int it = c_it[tp], jt = c_jt[tp];
            float* sa = sm.pp.sa;
            float* sb = sm.pp.sb;

            #pragma unroll
            for (int k = 0; k < 8; k++) {
                int idx = tid + k * 256;          // 0..2047 = 64 f x 32 rows
                int f = idx & 63;
                int row = idx >> 6;               // 0..31
                sa[f * PSROW + row] = g_proj[(size_t)(it * PT + row) * PP + fb + f];
                sb[f * PSROW + row] = g_proj[(size_t)(jt * PT + row) * PP + fb + f];
            }
            __syncthreads();

            int tx = tid & 15, ty = tid >> 4;
            float acc[2][2] = {{0.f, 0.f}, {0.f, 0.f}};
            #pragma unroll 8
            for (int f = 0; f < FC; f++) {
                float2 a = *(const float2*)&sa[f * PSROW + ty * 2];
                float2 b = *(const float2*)&sb[f * PSROW + tx * 2];
                acc[0][0] += fminf(a.x, b.x);
                acc[0][1] += fminf(a.x, b.y);
                acc[1][0] += fminf(a.y, b.x);
                acc[1][1] += fminf(a.y, b.y);
            }

            int ib = it * PT + ty * 2, jb = jt * PT + tx * 2;
            #pragma unroll
            for (int r = 0; r < 2; r++)
                #pragma unroll
                for (int c = 0; c < 2; c++) {
                    float v = -2.0f * acc[r][c];
                    atomicAdd(&out[(ib + r) * ND + (jb + c)], v);
                    if (it != jt)
                        atomicAdd(&out[(jb + c) * ND + (ib + r)], v);
                }
        } else {
            int e = (pid - PP_BLKS) * 256 + tid;  // 0..16383
            atomicAdd(&out[e], g_S[e >> 7] + g_S[e & 127]);
        }
    }
}

// ---------------------------------------------------------------- launch
extern "C" void kernel_launch(void* const* d_in, const int* in_sizes, int n_in,
                              void* d_out, int out_size) {
    const float* mass  = (const float*)d_in[0];   // (128, 10000) f32
    const float* param = (const float*)d_in[1];   // (2000, 10000) f32
    float* out = (float*)d_out;                   // (128, 128) f32

    k_init<<<64, 256>>>(out);
    k_mega<<<TOTAL, 256>>>(mass, param, out);
}

// round 14
// speedup vs baseline: 1.2295x; 1.2295x over previous
#include <cuda_runtime.h>
#include <cuda_fp16.h>

#define NI 2000      // inner tree nodes
#define NL 10000     // leaves / vocab
#define ND 128       // docs
#define PP 2048      // padded proj width
#define FC 64        // mass feature chunk
#define NMASS_CH 157 // ceil(NL/FC)
#define AG_BLKS 400  // argmax: 10 float4-col blocks x 40 row-chunks
#define AG_CH 50     // rows per argmax chunk
#define AG_RB 10     // load batch (MLP)
#define MP_BLKS (3 * NMASS_CH)   // 471 mass-pair blocks (ALL in fused2)
#define SROWH 68     // half2 row stride per feature-pair
// proj-pair: 32-doc tiles, 64-f chunks, 2x2 micro (R11-verified config)
#define PT 32
#define PSROW 36
#define NPP 10
#define PP_BLKS (NPP * (PP / FC))   // 320

__device__ unsigned long long g_amax[NL];
__device__ float g_proj[ND * PP];
__device__ float g_S[ND];

__constant__ int c_it[NPP] = {0,0,0,0,1,1,1,2,2,3};
__constant__ int c_jt[NPP] = {0,1,2,3,1,2,3,2,3,3};

__device__ __forceinline__ __half2 u2h2(unsigned u) {
    return *reinterpret_cast<__half2*>(&u);
}
__device__ __forceinline__ unsigned long long pack_key(float v, int idx) {
    unsigned u = __float_as_uint(v);
    u = (u & 0x80000000u) ? ~u : (u | 0x80000000u);
    return ((unsigned long long)u << 32) | (unsigned)idx;
}

// ---------------------------------------------------------------- init
__global__ void k_init(float* __restrict__ out) {
    int i = blockIdx.x * blockDim.x + threadIdx.x;
    if (i < NL) g_amax[i] = 0ull;
    if (i < ND * ND) out[i] = 0.0f;
    if (i < ND) g_S[i] = 0.0f;
}

// ---------------------------------------------------------------- pure argmax kernel (batch-10 MLP float4)
__global__ void __launch_bounds__(256)
k_argmax(const float* __restrict__ param) {
    int bid = blockIdx.x;
    int j4 = (bid % 10) * 256 + threadIdx.x;    // float4 column
    if (j4 >= NL / 4) return;
    int r0 = (bid / 10) * AG_CH;
    const float4* p = (const float4*)param + (size_t)r0 * (NL / 4) + j4;
    float4 bv = make_float4(-3.4e38f, -3.4e38f, -3.4e38f, -3.4e38f);
    int ix = r0, iy = r0, iz = r0, iw = r0;
    for (int rb = 0; rb < AG_CH; rb += AG_RB) {
        float4 v[AG_RB];
        #pragma unroll
        for (int k = 0; k < AG_RB; k++)
            v[k] = p[(size_t)(rb + k) * (NL / 4)];
        #pragma unroll
        for (int k = 0; k < AG_RB; k++) {
            int r = r0 + rb + k;
            if (v[k].x > bv.x) { bv.x = v[k].x; ix = r; }
            if (v[k].y > bv.y) { bv.y = v[k].y; iy = r; }
            if (v[k].z > bv.z) { bv.z = v[k].z; iz = r; }
            if (v[k].w > bv.w) { bv.w = v[k].w; iw = r; }
        }
    }
    int j = 4 * j4;
    atomicMax(&g_amax[j + 0], pack_key(bv.x, ix));
    atomicMax(&g_amax[j + 1], pack_key(bv.y, iy));
    atomicMax(&g_amax[j + 2], pack_key(bv.z, iz));
    atomicMax(&g_amax[j + 3], pack_key(bv.w, iw));
}

// ---------------------------------------------------------------- fused2: proj (128 blocks, ATOMS-bound) || ALL masspair (471, pipe-bound)
__global__ void __launch_bounds__(256)
k_fused2(const float* __restrict__ mass, float* __restrict__ out) {
    __shared__ union {
        struct { float s[NI]; float red[256]; } pj;
        __half2 mp[2][32 * SROWH];
    } sm;
    int tid = threadIdx.x;

    if (blockIdx.x < ND) {
        // ---- proj for doc d: shared scatter + bottom-up tree-sum ----
        int d = blockIdx.x;
        float* s = sm.pj.s;
        for (int i = tid; i < NI; i += 256) s[i] = 0.0f;
        __syncthreads();
        const float4* m4 = (const float4*)(mass + (size_t)d * NL);
        float msum = 0.0f;
        for (int j4 = tid; j4 < NL / 4; j4 += 256) {
            float4 v = m4[j4];
            msum += v.x + v.y + v.z + v.w;
            int a0 = (int)(unsigned)(__ldg(&g_amax[4 * j4 + 0]) & 0xFFFFFFFFull);
            int a1 = (int)(unsigned)(__ldg(&g_amax[4 * j4 + 1]) & 0xFFFFFFFFull);
            int a2 = (int)(unsigned)(__ldg(&g_amax[4 * j4 + 2]) & 0xFFFFFFFFull);
            int a3 = (int)(unsigned)(__ldg(&g_amax[4 * j4 + 3]) & 0xFFFFFFFFull);
            atomicAdd(&s[a0], v.x);
            atomicAdd(&s[a1], v.y);
            atomicAdd(&s[a2], v.z);
            atomicAdd(&s[a3], v.w);
        }
        __syncthreads();
        // bottom-up: parents {156..399},{31..155},{6..30},{1..5},{0}
        const int lo[5] = {156, 31, 6, 1, 0};
        const int hi[5] = {399, 155, 30, 5, 0};
        for (int L = 0; L < 5; L++) {
            for (int p = lo[L] + tid; p <= hi[L]; p += 256) {
                float acc = s[p];
                int c0 = 5 * p + 1;
                #pragma unroll
                for (int c = 0; c < 5; c++)
                    if (c0 + c < NI) acc += s[c0 + c];
                s[p] = acc;
            }
            __syncthreads();
        }
        float psum = 0.0f;
        for (int i = tid; i < NI; i += 256) psum += s[i];
        sm.pj.red[tid] = msum + psum;
        __syncthreads();
        for (int w = 128; w > 0; w >>= 1) {
            if (tid < w) sm.pj.red[tid] += sm.pj.red[tid + w];
            __syncthreads();
        }
        if (tid == 0) g_S[d] = sm.pj.red[0];
        float* gp = g_proj + (size_t)d * PP;
        for (int i = tid; i < PP; i += 256)
            gp[i] = (i < NI) ? s[i] : 0.0f;
    } else {
        // ---- fp16 mass-pair: one 64-f chunk, one 64x64 tile-pair ----
        int pid = blockIdx.x - ND;        // 0..470
        int tp = pid % 3;                 // 0:(0,0) 1:(0,1)+mirror 2:(1,1)
        int chunk = pid / 3;
        int fb = chunk * FC;
        int nh = min(FC, NL - fb) >> 1;
        int it = (tp == 2) ? 1 : 0;
        int jt = (tp == 0) ? 0 : 1;
        __half2* sa2 = sm.mp[0];
        __half2* sb2 = sm.mp[1];

        const __half2 hz = __float2half2_rn(0.0f);
        #pragma unroll
        for (int k = 0; k < 8; k++) {
            int idx = tid + k * 256;          // 0..2047
            int f2 = idx & 31;
            int row = idx >> 5;               // 0..63
            __half2 ha = hz, hb = hz;
            if (f2 < nh) {
                float2 va = *(const float2*)&mass[(size_t)(it * 64 + row) * NL + fb + 2 * f2];
                float2 vb = *(const float2*)&mass[(size_t)(jt * 64 + row) * NL + fb + 2 * f2];
                ha = __floats2half2_rn(va.x, va.y);
                hb = __floats2half2_rn(vb.x, vb.y);
            }
            sa2[f2 * SROWH + row] = ha;
            sb2[f2 * SROWH + row] = hb;
        }
        __syncthreads();

        int tx = tid & 15, ty = tid >> 4;
        __half2 acc[4][4];
        #pragma unroll
        for (int r = 0; r < 4; r++)
            #pragma unroll
            for (int c = 0; c < 4; c++) acc[r][c] = hz;

        #pragma unroll 4
        for (int f2 = 0; f2 < 32; f2++) {
            uint4 ua = *(const uint4*)&sa2[f2 * SROWH + ty * 4];
            uint4 ub = *(const uint4*)&sb2[f2 * SROWH + tx * 4];
            __half2 ar[4] = {u2h2(ua.x), u2h2(ua.y), u2h2(ua.z), u2h2(ua.w)};
            __half2 br[4] = {u2h2(ub.x), u2h2(ub.y), u2h2(ub.z), u2h2(ub.w)};
            #pragma unroll
            for (int r = 0; r < 4; r++)
                #pragma unroll
                for (int c = 0; c < 4; c++)
                    acc[r][c] = __hadd2(acc[r][c], __hmin2(ar[r], br[c]));
        }

        int ib = it * 64 + ty * 4, jb = jt * 64 + tx * 4;
        #pragma unroll
        for (int r = 0; r < 4; r++)
            #pragma unroll
            for (int c = 0; c < 4; c++) {
                float2 f = __half22float2(acc[r][c]);
                float v = -2.0f * (f.x + f.y);
                atomicAdd(&out[(ib + r) * ND + (jb + c)], v);
                if (tp == 1)
                    atomicAdd(&out[(jb + c) * ND + (ib + r)], v);
            }
    }
}

// ---------------------------------------------------------------- fp32 proj-pair (32-tiles, 64-f chunks, 2x2) || S epilogue
__global__ void __launch_bounds__(256)
k_projpair(float* __restrict__ out) {
    __shared__ float sa[FC * PSROW];
    __shared__ float sb[FC * PSROW];
    if (blockIdx.x < PP_BLKS) {
        int pid = blockIdx.x;
        int tp = pid % NPP;
        int fb = (pid / NPP) * FC;
        int it = c_it[tp], jt = c_jt[tp];
        int tid = threadIdx.x;

        #pragma unroll
        for (int k = 0; k < 8; k++) {
            int idx = tid + k * 256;          // 0..2047 = 64 f x 32 rows
            int f = idx & 63;
            int row = idx >> 6;               // 0..31
            sa[f * PSROW + row] = g_proj[(size_t)(it * PT + row) * PP + fb + f];
            sb[f * PSROW + row] = g_proj[(size_t)(jt * PT + row) * PP + fb + f];
        }
        __syncthreads();

        int tx = tid & 15, ty = tid >> 4;
        float acc[2][2] = {{0.f, 0.f}, {0.f, 0.f}};
        #pragma unroll 8
        for (int f = 0; f < FC; f++) {
            float2 a = *(const float2*)&sa[f * PSROW + ty * 2];
            float2 b = *(const float2*)&sb[f * PSROW + tx * 2];
            acc[0][0] += fminf(a.x, b.x);
            acc[0][1] += fminf(a.x, b.y);
            acc[1][0] += fminf(a.y, b.x);
            acc[1][1] += fminf(a.y, b.y);
        }

        int ib = it * PT + ty * 2, jb = jt * PT + tx * 2;
        #pragma unroll
        for (int r = 0; r < 2; r++)
            #pragma unroll
            for (int c = 0; c < 2; c++) {
                float v = -2.0f * acc[r][c];
                atomicAdd(&out[(ib + r) * ND + (jb + c)], v);
                if (it != jt)
                    atomicAdd(&out[(jb + c) * ND + (ib + r)], v);
            }
    } else {
        int e = (blockIdx.x - PP_BLKS) * 256 + threadIdx.x;  // 0..16383
        atomicAdd(&out[e], g_S[e >> 7] + g_S[e & 127]);
    }
}

// ---------------------------------------------------------------- launch
extern "C" void kernel_launch(void* const* d_in, const int* in_sizes, int n_in,
                              void* d_out, int out_size) {
    const float* mass  = (const float*)d_in[0];   // (128, 10000) f32
    const float* param = (const float*)d_in[1];   // (2000, 10000) f32
    float* out = (float*)d_out;                   // (128, 128) f32

    k_init<<<64, 256>>>(out);
    k_argmax<<<AG_BLKS, 256>>>(param);
    k_fused2<<<ND + MP_BLKS, 256>>>(mass, out);
    k_projpair<<<PP_BLKS + (ND * ND) / 256, 256>>>(out);
}

// round 15
// speedup vs baseline: 1.2371x; 1.0062x over previous
#include <cuda_runtime.h>
#include <cuda_fp16.h>

#define NI 2000      // inner tree nodes
#define NL 10000     // leaves / vocab
#define ND 128       // docs
#define PP 2048      // padded proj width
#define FC 64        // mass feature chunk
#define NMASS_CH 157 // ceil(NL/FC)
#define AG_BLKS 400  // argmax: 10 float4-col blocks x 40 row-chunks
#define AG_CH 50     // rows per argmax chunk
#define AG_RB 10     // load batch (MLP)
#define MP_BLKS (3 * NMASS_CH)   // 471 mass-pair blocks
#define SROWH 68     // half2 row stride per feature-pair
// proj scatter: 2 leaf-slices per doc
#define SC_BLKS (2 * ND)          // 256
#define SL4 1250                  // float4-leaves per slice (2500/2)
// proj-pair: 32-doc tiles, 64-f chunks, 2x2 micro (verified config)
#define PT 32
#define PSROW 36
#define NPP 10
#define PP_BLKS (NPP * (PP / FC))   // 320

__device__ unsigned long long g_amax[NL];
__device__ float g_proj[ND * PP];
__device__ float g_S[ND];

__constant__ int c_it[NPP] = {0,0,0,0,1,1,1,2,2,3};
__constant__ int c_jt[NPP] = {0,1,2,3,1,2,3,2,3,3};

__device__ __forceinline__ __half2 u2h2(unsigned u) {
    return *reinterpret_cast<__half2*>(&u);
}
__device__ __forceinline__ unsigned long long pack_key(float v, int idx) {
    unsigned u = __float_as_uint(v);
    u = (u & 0x80000000u) ? ~u : (u | 0x80000000u);
    return ((unsigned long long)u << 32) | (unsigned)idx;
}
__device__ __forceinline__ void red4(float* p, float4 v) {
    asm volatile("red.global.add.v4.f32 [%0], {%1,%2,%3,%4};"
                 :: "l"(p), "f"(v.x), "f"(v.y), "f"(v.z), "f"(v.w) : "memory");
}

// ---------------------------------------------------------------- init
__global__ void k_init(float* __restrict__ out) {
    int i = blockIdx.x * blockDim.x + threadIdx.x;
    if (i < ND * PP) g_proj[i] = 0.0f;
    if (i < NL) g_amax[i] = 0ull;
    if (i < ND * ND) out[i] = 0.0f;
    if (i < ND) g_S[i] = 0.0f;
}

// ---------------------------------------------------------------- pure argmax kernel (batch-10 MLP float4)
__global__ void __launch_bounds__(256)
k_argmax(const float* __restrict__ param) {
    int bid = blockIdx.x;
    int j4 = (bid % 10) * 256 + threadIdx.x;    // float4 column
    if (j4 >= NL / 4) return;
    int r0 = (bid / 10) * AG_CH;
    const float4* p = (const float4*)param + (size_t)r0 * (NL / 4) + j4;
    float4 bv = make_float4(-3.4e38f, -3.4e38f, -3.4e38f, -3.4e38f);
    int ix = r0, iy = r0, iz = r0, iw = r0;
    for (int rb = 0; rb < AG_CH; rb += AG_RB) {
        float4 v[AG_RB];
        #pragma unroll
        for (int k = 0; k < AG_RB; k++)
            v[k] = p[(size_t)(rb + k) * (NL / 4)];
        #pragma unroll
        for (int k = 0; k < AG_RB; k++) {
            int r = r0 + rb + k;
            if (v[k].x > bv.x) { bv.x = v[k].x; ix = r; }
            if (v[k].y > bv.y) { bv.y = v[k].y; iy = r; }
            if (v[k].z > bv.z) { bv.z = v[k].z; iz = r; }
            if (v[k].w > bv.w) { bv.w = v[k].w; iw = r; }
        }
    }
    int j = 4 * j4;
    atomicMax(&g_amax[j + 0], pack_key(bv.x, ix));
    atomicMax(&g_amax[j + 1], pack_key(bv.y, iy));
    atomicMax(&g_amax[j + 2], pack_key(bv.z, iz));
    atomicMax(&g_amax[j + 3], pack_key(bv.w, iw));
}

// ---------------------------------------------------------------- fused2: proj (2 slices/doc, 256 blocks) || ALL masspair (471)
__global__ void __launch_bounds__(256)
k_fused2(const float* __restrict__ mass, float* __restrict__ out) {
    __shared__ union {
        struct { float s[NI]; float red[256]; } pj;
        __half2 mp[2][32 * SROWH];
    } sm;
    int tid = threadIdx.x;

    if (blockIdx.x < SC_BLKS) {
        // ---- proj slice: scatter half the leaves of doc d, tree-sum, REDG-merge ----
        int d = blockIdx.x >> 1;
        int sl = blockIdx.x & 1;
        float* s = sm.pj.s;
        for (int i = tid; i < NI; i += 256) s[i] = 0.0f;
        __syncthreads();
        const float4* m4 = (const float4*)(mass + (size_t)d * NL);
        int base = sl * SL4;
        for (int j4 = base + tid; j4 < base + SL4; j4 += 256) {
            float4 v = m4[j4];
            int a0 = (int)(unsigned)(__ldg(&g_amax[4 * j4 + 0]) & 0xFFFFFFFFull);
            int a1 = (int)(unsigned)(__ldg(&g_amax[4 * j4 + 1]) & 0xFFFFFFFFull);
            int a2 = (int)(unsigned)(__ldg(&g_amax[4 * j4 + 2]) & 0xFFFFFFFFull);
            int a3 = (int)(unsigned)(__ldg(&g_amax[4 * j4 + 3]) & 0xFFFFFFFFull);
            atomicAdd(&s[a0], v.x);
            atomicAdd(&s[a1], v.y);
            atomicAdd(&s[a2], v.z);
            atomicAdd(&s[a3], v.w);
        }
        __syncthreads();
        // bottom-up (linear => per-slice partials sum correctly):
        const int lo[5] = {156, 31, 6, 1, 0};
        const int hi[5] = {399, 155, 30, 5, 0};
        for (int L = 0; L < 5; L++) {
            for (int p = lo[L] + tid; p <= hi[L]; p += 256) {
                float acc = s[p];
                int c0 = 5 * p + 1;
                #pragma unroll
                for (int c = 0; c < 5; c++)
                    if (c0 + c < NI) acc += s[c0 + c];
                s[p] = acc;
            }
            __syncthreads();
        }
        // merge into g_proj + S partial
        float psum = 0.0f;
        float* gp = g_proj + (size_t)d * PP;
        for (int i = tid * 4; i < NI; i += 1024) {
            float4 a = *(float4*)&s[i];
            psum += a.x + a.y + a.z + a.w;
            red4(&gp[i], a);
        }
        sm.pj.red[tid] = psum;
        __syncthreads();
        for (int w = 128; w > 0; w >>= 1) {
            if (tid < w) sm.pj.red[tid] += sm.pj.red[tid + w];
            __syncthreads();
        }
        if (tid == 0) atomicAdd(&g_S[d], sm.pj.red[0]);
    } else {
        // ---- fp16 mass-pair: one 64-f chunk, one 64x64 tile-pair ----
        int pid = blockIdx.x - SC_BLKS;   // 0..470
        int tp = pid % 3;                 // 0:(0,0) 1:(0,1)+mirror 2:(1,1)
        int chunk = pid / 3;
        int fb = chunk * FC;
        int nh = min(FC, NL - fb) >> 1;
        int it = (tp == 2) ? 1 : 0;
        int jt = (tp == 0) ? 0 : 1;
        __half2* sa2 = sm.mp[0];
        __half2* sb2 = sm.mp[1];

        const __half2 hz = __float2half2_rn(0.0f);
        #pragma unroll
        for (int k = 0; k < 8; k++) {
            int idx = tid + k * 256;          // 0..2047
            int f2 = idx & 31;
            int row = idx >> 5;               // 0..63
            __half2 ha = hz, hb = hz;
            if (f2 < nh) {
                float2 va = *(const float2*)&mass[(size_t)(it * 64 + row) * NL + fb + 2 * f2];
                float2 vb = *(const float2*)&mass[(size_t)(jt * 64 + row) * NL + fb + 2 * f2];
                ha = __floats2half2_rn(va.x, va.y);
                hb = __floats2half2_rn(vb.x, vb.y);
            }
            sa2[f2 * SROWH + row] = ha;
            sb2[f2 * SROWH + row] = hb;
        }
        __syncthreads();

        int tx = tid & 15, ty = tid >> 4;
        __half2 acc[4][4];
        #pragma unroll
        for (int r = 0; r < 4; r++)
            #pragma unroll
            for (int c = 0; c < 4; c++) acc[r][c] = hz;

        #pragma unroll 4
        for (int f2 = 0; f2 < 32; f2++) {
            uint4 ua = *(const uint4*)&sa2[f2 * SROWH + ty * 4];
            uint4 ub = *(const uint4*)&sb2[f2 * SROWH + tx * 4];
            __half2 ar[4] = {u2h2(ua.x), u2h2(ua.y), u2h2(ua.z), u2h2(ua.w)};
            __half2 br[4] = {u2h2(ub.x), u2h2(ub.y), u2h2(ub.z), u2h2(ub.w)};
            #pragma unroll
            for (int r = 0; r < 4; r++)
                #pragma unroll
                for (int c = 0; c < 4; c++)
                    acc[r][c] = __hadd2(acc[r][c], __hmin2(ar[r], br[c]));
        }

        int ib = it * 64 + ty * 4, jb = jt * 64 + tx * 4;
        #pragma unroll
        for (int r = 0; r < 4; r++)
            #pragma unroll
            for (int c = 0; c < 4; c++) {
                float2 f = __half22float2(acc[r][c]);
                float v = -2.0f * (f.x + f.y);
                atomicAdd(&out[(ib + r) * ND + (jb + c)], v);
                if (tp == 1)
                    atomicAdd(&out[(jb + c) * ND + (ib + r)], v);
            }
    }
}

// ---------------------------------------------------------------- fp32 proj-pair (32-tiles, 64-f chunks, 2x2) || S epilogue (+2 mass sums)
__global__ void __launch_bounds__(256)
k_projpair(float* __restrict__ out) {
    __shared__ float sa[FC * PSROW];
    __shared__ float sb[FC * PSROW];
    if (blockIdx.x < PP_BLKS) {
        int pid = blockIdx.x;
        int tp = pid % NPP;
        int fb = (pid / NPP) * FC;
        int it = c_it[tp], jt = c_jt[tp];
        int tid = threadIdx.x;

        #pragma unroll
        for (int k = 0; k < 8; k++) {
            int idx = tid + k * 256;          // 0..2047 = 64 f x 32 rows
            int f = idx & 63;
            int row = idx >> 6;               // 0..31
            sa[f * PSROW + row] = g_proj[(size_t)(it * PT + row) * PP + fb + f];
            sb[f * PSROW + row] = g_proj[(size_t)(jt * PT + row) * PP + fb + f];
        }
        __syncthreads();

        int tx = tid & 15, ty = tid >> 4;
        float acc[2][2] = {{0.f, 0.f}, {0.f, 0.f}};
        #pragma unroll 8
        for (int f = 0; f < FC; f++) {
            float2 a = *(const float2*)&sa[f * PSROW + ty * 2];
            float2 b = *(const float2*)&sb[f * PSROW + tx * 2];
            acc[0][0] += fminf(a.x, b.x);
            acc[0][1] += fminf(a.x, b.y);
            acc[1][0] += fminf(a.y, b.x);
            acc[1][1] += fminf(a.y, b.y);
        }

        int ib = it * PT + ty * 2, jb = jt * PT + tx * 2;
        #pragma unroll
        for (int r = 0; r < 2; r++)
            #pragma unroll
            for (int c = 0; c < 2; c++) {
                float v = -2.0f * acc[r][c];
                atomicAdd(&out[(ib + r) * ND + (jb + c)], v);
                if (it != jt)
                    atomicAdd(&out[(jb + c) * ND + (ib + r)], v);
            }
    } else {
        int e = (blockIdx.x - PP_BLKS) * 256 + threadIdx.x;  // 0..16383
        // +2.0f = sum(mass_i) + sum(mass_j) (each doc's mass sums to 1)
        atomicAdd(&out[e], g_S[e >> 7] + g_S[e & 127] + 2.0f);
    }
}

// ---------------------------------------------------------------- launch
extern "C" void kernel_launch(void* const* d_in, const int* in_sizes, int n_in,
                              void* d_out, int out_size) {
    const float* mass  = (const float*)d_in[0];   // (128, 10000) f32
    const float* param = (const float*)d_in[1];   // (2000, 10000) f32
    float* out = (float*)d_out;                   // (128, 128) f32

    k_init<<<1024, 256>>>(out);
    k_argmax<<<AG_BLKS, 256>>>(param);
    k_fused2<<<SC_BLKS + MP_BLKS, 256>>>(mass, out);
    k_projpair<<<PP_BLKS + (ND * ND) / 256, 256>>>(out);
}

// round 16
// speedup vs baseline: 1.2867x; 1.0402x over previous
#include <cuda_runtime.h>
#include <cuda_fp16.h>

#define NI 2000      // inner tree nodes
#define NL 10000     // leaves / vocab
#define ND 128       // docs
#define PP 2048      // padded proj width
#define FC 64        // mass feature chunk
#define NMASS_CH 157 // ceil(NL/FC)
#define AG_BLKS 400  // argmax: 10 float4-col blocks x 40 row-chunks
#define AG_CH 50     // rows per argmax chunk
#define AG_RB 10     // load batch (MLP)
#define MP_BLKS (3 * NMASS_CH)   // 471 mass-pair blocks
#define SROWH 68     // half2 row stride per feature-pair
// proj scatter: 2 leaf-slices per doc
#define SC_BLKS (2 * ND)          // 256
#define SL4 1250                  // float4-leaves per slice
// proj-pair: 32-doc tiles, 64-f chunks, 2x2 micro (verified config)
#define PT 32
#define PSROW 36
#define NPP 10
#define PP_BLKS (NPP * (PP / FC))   // 320

__device__ unsigned long long g_amax[NL];
__device__ float g_proj[ND * PP];
__device__ float g_S[ND];

__constant__ int c_it[NPP] = {0,0,0,0,1,1,1,2,2,3};
__constant__ int c_jt[NPP] = {0,1,2,3,1,2,3,2,3,3};

__device__ __forceinline__ __half2 u2h2(unsigned u) {
    return *reinterpret_cast<__half2*>(&u);
}
__device__ __forceinline__ unsigned long long pack_key(float v, int idx) {
    unsigned u = __float_as_uint(v);
    u = (u & 0x80000000u) ? ~u : (u | 0x80000000u);
    return ((unsigned long long)u << 32) | (unsigned)idx;
}
__device__ __forceinline__ void red4(float* p, float4 v) {
    asm volatile("red.global.add.v4.f32 [%0], {%1,%2,%3,%4};"
                 :: "l"(p), "f"(v.x), "f"(v.y), "f"(v.z), "f"(v.w) : "memory");
}

// ---------------------------------------------------------------- init
__global__ void k_init(float* __restrict__ out) {
    int i = blockIdx.x * blockDim.x + threadIdx.x;
    if (i < ND * PP) g_proj[i] = 0.0f;
    if (i < NL) g_amax[i] = 0ull;
    if (i < ND * ND) out[i] = 0.0f;
    if (i < ND) g_S[i] = 0.0f;
}

// ---------------------------------------------------------------- fused1: argmax || masspair; all input-indep work PRE-sync
__global__ void __launch_bounds__(256)
k_fused1(const float* __restrict__ mass, const float* __restrict__ param,
         float* __restrict__ out) {
    __shared__ __half2 smp[2][32 * SROWH];
    int tid = threadIdx.x;

    if (blockIdx.x < AG_BLKS) {
        // ---- scan param (independent of init) ----
        int bid = blockIdx.x;
        int j4 = (bid % 10) * 256 + tid;
        bool ok = j4 < NL / 4;
        int j4c = ok ? j4 : (NL / 4 - 1);
        int r0 = (bid / 10) * AG_CH;
        const float4* p = (const float4*)param + (size_t)r0 * (NL / 4) + j4c;
        float4 bv = make_float4(-3.4e38f, -3.4e38f, -3.4e38f, -3.4e38f);
        int ix = r0, iy = r0, iz = r0, iw = r0;
        for (int rb = 0; rb < AG_CH; rb += AG_RB) {
            float4 v[AG_RB];
            #pragma unroll
            for (int k = 0; k < AG_RB; k++)
                v[k] = p[(size_t)(rb + k) * (NL / 4)];
            #pragma unroll
            for (int k = 0; k < AG_RB; k++) {
                int r = r0 + rb + k;
                if (v[k].x > bv.x) { bv.x = v[k].x; ix = r; }
                if (v[k].y > bv.y) { bv.y = v[k].y; iy = r; }
                if (v[k].z > bv.z) { bv.z = v[k].z; iz = r; }
                if (v[k].w > bv.w) { bv.w = v[k].w; iw = r; }
            }
        }
        cudaGridDependencySynchronize();   // wait: init zeroed g_amax
        if (ok) {
            int j = 4 * j4;
            atomicMax(&g_amax[j + 0], pack_key(bv.x, ix));
            atomicMax(&g_amax[j + 1], pack_key(bv.y, iy));
            atomicMax(&g_amax[j + 2], pack_key(bv.z, iz));
            atomicMax(&g_amax[j + 3], pack_key(bv.w, iw));
        }
    } else {
        // ---- fp16 mass-pair: full compute pre-sync, atomics post-sync ----
        int pid = blockIdx.x - AG_BLKS;   // 0..470
        int tp = pid % 3;                 // 0:(0,0) 1:(0,1)+mirror 2:(1,1)
        int chunk = pid / 3;
        int fb = chunk * FC;
        int nh = min(FC, NL - fb) >> 1;
        int it = (tp == 2) ? 1 : 0;
        int jt = (tp == 0) ? 0 : 1;
        __half2* sa2 = smp[0];
        __half2* sb2 = smp[1];

        const __half2 hz = __float2half2_rn(0.0f);
        #pragma unroll
        for (int k = 0; k < 8; k++) {
            int idx = tid + k * 256;          // 0..2047
            int f2 = idx & 31;
            int row = idx >> 5;               // 0..63
            __half2 ha = hz, hb = hz;
            if (f2 < nh) {
                float2 va = *(const float2*)&mass[(size_t)(it * 64 + row) * NL + fb + 2 * f2];
                float2 vb = *(const float2*)&mass[(size_t)(jt * 64 + row) * NL + fb + 2 * f2];
                ha = __floats2half2_rn(va.x, va.y);
                hb = __floats2half2_rn(vb.x, vb.y);
            }
            sa2[f2 * SROWH + row] = ha;
            sb2[f2 * SROWH + row] = hb;
        }
        __syncthreads();

        int tx = tid & 15, ty = tid >> 4;
        __half2 acc[4][4];
        #pragma unroll
        for (int r = 0; r < 4; r++)
            #pragma unroll
            for (int c = 0; c < 4; c++) acc[r][c] = hz;

        #pragma unroll 4
        for (int f2 = 0; f2 < 32; f2++) {
            uint4 ua = *(const uint4*)&sa2[f2 * SROWH + ty * 4];
            uint4 ub = *(const uint4*)&sb2[f2 * SROWH + tx * 4];
            __half2 ar[4] = {u2h2(ua.x), u2h2(ua.y), u2h2(ua.z), u2h2(ua.w)};
            __half2 br[4] = {u2h2(ub.x), u2h2(ub.y), u2h2(ub.z), u2h2(ub.w)};
            #pragma unroll
            for (int r = 0; r < 4; r++)
                #pragma unroll
                for (int c = 0; c < 4; c++)
                    acc[r][c] = __hadd2(acc[r][c], __hmin2(ar[r], br[c]));
        }

        cudaGridDependencySynchronize();   // wait: init zeroed out
        int ib = it * 64 + ty * 4, jb = jt * 64 + tx * 4;
        #pragma unroll
        for (int r = 0; r < 4; r++)
            #pragma unroll
            for (int c = 0; c < 4; c++) {
                float2 f = __half22float2(acc[r][c]);
                float v = -2.0f * (f.x + f.y);
                atomicAdd(&out[(ib + r) * ND + (jb + c)], v);
                if (tp == 1)
                    atomicAdd(&out[(jb + c) * ND + (ib + r)], v);
            }
    }
}

// ---------------------------------------------------------------- proj: 2 slices/doc, scatter + tree-sum + REDG merge
__global__ void __launch_bounds__(256)
k_proj(const float* __restrict__ mass) {
    __shared__ float s[NI];
    __shared__ float red[256];
    int tid = threadIdx.x;
    int d = blockIdx.x >> 1;
    int sl = blockIdx.x & 1;
    for (int i = tid; i < NI; i += 256) s[i] = 0.0f;
    cudaGridDependencySynchronize();   // wait: fused1 wrote g_amax (transitively init)
    __syncthreads();
    const float4* m4 = (const float4*)(mass + (size_t)d * NL);
    int base = sl * SL4;
    for (int j4 = base + tid; j4 < base + SL4; j4 += 256) {
        float4 v = m4[j4];
        int a0 = (int)(unsigned)(__ldg(&g_amax[4 * j4 + 0]) & 0xFFFFFFFFull);
        int a1 = (int)(unsigned)(__ldg(&g_amax[4 * j4 + 1]) & 0xFFFFFFFFull);
        int a2 = (int)(unsigned)(__ldg(&g_amax[4 * j4 + 2]) & 0xFFFFFFFFull);
        int a3 = (int)(unsigned)(__ldg(&g_amax[4 * j4 + 3]) & 0xFFFFFFFFull);
        atomicAdd(&s[a0], v.x);
        atomicAdd(&s[a1], v.y);
        atomicAdd(&s[a2], v.z);
        atomicAdd(&s[a3], v.w);
    }
    __syncthreads();
    // bottom-up (linear => per-slice partials sum correctly)
    const int lo[5] = {156, 31, 6, 1, 0};
    const int hi[5] = {399, 155, 30, 5, 0};
    for (int L = 0; L < 5; L++) {
        for (int p = lo[L] + tid; p <= hi[L]; p += 256) {
            float acc = s[p];
            int c0 = 5 * p + 1;
            #pragma unroll
            for (int c = 0; c < 5; c++)
                if (c0 + c < NI) acc += s[c0 + c];
            s[p] = acc;
        }
        __syncthreads();
    }
    // merge into g_proj + S partial
    float psum = 0.0f;
    float* gp = g_proj + (size_t)d * PP;
    for (int i = tid * 4; i < NI; i += 1024) {
        float4 a = *(float4*)&s[i];
        psum += a.x + a.y + a.z + a.w;
        red4(&gp[i], a);
    }
    red[tid] = psum;
    __syncthreads();
    for (int w = 128; w > 0; w >>= 1) {
        if (tid < w) red[tid] += red[tid + w];
        __syncthreads();
    }
    if (tid == 0) atomicAdd(&g_S[d], red[0]);
}

// ---------------------------------------------------------------- fp32 proj-pair || S epilogue (+2 mass sums)
__global__ void __launch_bounds__(256)
k_projpair(float* __restrict__ out) {
    __shared__ float sa[FC * PSROW];
    __shared__ float sb[FC * PSROW];
    cudaGridDependencySynchronize();   // wait: proj wrote g_proj, g_S
    if (blockIdx.x < PP_BLKS) {
        int pid = blockIdx.x;
        int tp = pid % NPP;
        int fb = (pid / NPP) * FC;
        int it = c_it[tp], jt = c_jt[tp];
        int tid = threadIdx.x;

        #pragma unroll
        for (int k = 0; k < 8; k++) {
            int idx = tid + k * 256;          // 0..2047 = 64 f x 32 rows
            int f = idx & 63;
            int row = idx >> 6;               // 0..31
            sa[f * PSROW + row] = g_proj[(size_t)(it * PT + row) * PP + fb + f];
            sb[f * PSROW + row] = g_proj[(size_t)(jt * PT + row) * PP + fb + f];
        }
        __syncthreads();

        int tx = tid & 15, ty = tid >> 4;
        float acc[2][2] = {{0.f, 0.f}, {0.f, 0.f}};
        #pragma unroll 8
        for (int f = 0; f < FC; f++) {
            float2 a = *(const float2*)&sa[f * PSROW + ty * 2];
            float2 b = *(const float2*)&sb[f * PSROW + tx * 2];
            acc[0][0] += fminf(a.x, b.x);
            acc[0][1] += fminf(a.x, b.y);
            acc[1][0] += fminf(a.y, b.x);
            acc[1][1] += fminf(a.y, b.y);
        }

        int ib = it * PT + ty * 2, jb = jt * PT + tx * 2;
        #pragma unroll
        for (int r = 0; r < 2; r++)
            #pragma unroll
            for (int c = 0; c < 2; c++) {
                float v = -2.0f * acc[r][c];
                atomicAdd(&out[(ib + r) * ND + (jb + c)], v);
                if (it != jt)
                    atomicAdd(&out[(jb + c) * ND + (ib + r)], v);
            }
    } else {
        int e = (blockIdx.x - PP_BLKS) * 256 + threadIdx.x;  // 0..16383
        // +2.0f = sum(mass_i) + sum(mass_j) (each doc's mass sums to 1)
        atomicAdd(&out[e], g_S[e >> 7] + g_S[e & 127] + 2.0f);
    }
}

// ---------------------------------------------------------------- launch (PDL chain)
extern "C" void kernel_launch(void* const* d_in, const int* in_sizes, int n_in,
                              void* d_out, int out_size) {
    const float* mass  = (const float*)d_in[0];   // (128, 10000) f32
    const float* param = (const float*)d_in[1];   // (2000, 10000) f32
    float* out = (float*)d_out;                   // (128, 128) f32

    k_init<<<1024, 256>>>(out);

    cudaLaunchConfig_t cfg = {};
    cfg.blockDim = {256, 1, 1};
    cfg.stream = 0;
    cudaLaunchAttribute attr;
    attr.id = cudaLaunchAttributeProgrammaticStreamSerialization;
    attr.val.programmaticStreamSerializationAllowed = 1;
    cfg.attrs = &attr;
    cfg.numAttrs = 1;

    cfg.gridDim = {AG_BLKS + MP_BLKS, 1, 1};
    cudaLaunchKernelEx(&cfg, k_fused1, mass, param, out);

    cfg.gridDim = {SC_BLKS, 1, 1};
    cudaLaunchKernelEx(&cfg, k_proj, mass);

    cfg.gridDim = {PP_BLKS + (ND * ND) / 256, 1, 1};
    cudaLaunchKernelEx(&cfg, k_projpair, out);
}